// round 1
// baseline (speedup 1.0000x reference)
#include <cuda_runtime.h>
#include <cstdint>

#define BB 32
#define CC 8
#define HH 300
#define WW 300
#define HW (HH*WW)

// ---------------- device scratch (no allocs allowed) ----------------
__device__ float g_buf[69120000];          // [32][24][300][300] = 276.5 MB
__device__ float p5_buf[BB*CC*60*60];      // 921600
__device__ float p10_buf[BB*CC*30*30];     // 230400
__device__ float p15_buf[BB*CC*20*20];     // 102400
__device__ float part_buf[3200*16];        // per-block (sum[8], sumsq[8])
__device__ float bn_buf[16];               // scale[8], shift[8]

// ---------------- K1a: 5x5 average pool ----------------
__global__ void k_pool5(const float* __restrict__ x) {
    int i = blockIdx.x * blockDim.x + threadIdx.x;
    if (i >= BB*CC*60*60) return;
    int px = i % 60; int t = i / 60;
    int py = t % 60; t /= 60;
    int c  = t % 8;  int b = t / 8;
    const float* base = x + ((size_t)(b*8 + c)*HH + py*5)*WW + px*5;
    float s = 0.f;
    #pragma unroll
    for (int r = 0; r < 5; r++)
        #pragma unroll
        for (int q = 0; q < 5; q++) s += base[r*WW + q];
    p5_buf[i] = s * (1.0f/25.0f);
}

// ---------------- K1b: pool10 / pool15 from pool5 (exact) ----------------
__global__ void k_poolrest() {
    int i = blockIdx.x * blockDim.x + threadIdx.x;
    if (i < BB*CC*30*30) {
        int px = i % 30; int t = i / 30;
        int py = t % 30; t /= 30;
        int c  = t % 8;  int b = t / 8;
        const float* base = p5_buf + ((b*8 + c)*60 + py*2)*60 + px*2;
        p10_buf[i] = (base[0] + base[1] + base[60] + base[61]) * 0.25f;
    }
    int j = i - BB*CC*30*30;
    if (j >= 0 && j < BB*CC*20*20) {
        int px = j % 20; int t = j / 20;
        int py = t % 20; t /= 20;
        int c  = t % 8;  int b = t / 8;
        const float* base = p5_buf + ((b*8 + c)*60 + py*3)*60 + px*3;
        float s = 0.f;
        #pragma unroll
        for (int r = 0; r < 3; r++)
            #pragma unroll
            for (int q = 0; q < 3; q++) s += base[r*60 + q];
        p15_buf[j] = s * (1.0f/9.0f);
    }
}

// ---------------- K2a: three concat-convs -> g_in ----------------
// tile: 30x30 output, 32x32 input (halo 1). grid (10,10,32), 256 threads.
// dyn smem: xs[8*32*32] + us[8*32*32] + ws[1152] + bs[8] = 17544 floats
__global__ void k_conv1(const float* __restrict__ x,
                        const float* __restrict__ w5,  const float* __restrict__ b5,
                        const float* __restrict__ w10, const float* __restrict__ b10,
                        const float* __restrict__ w15, const float* __restrict__ b15) {
    extern __shared__ float sm[];
    float* xs = sm;              // 8192
    float* us = sm + 8192;       // 8192
    float* ws = sm + 16384;      // 1152
    float* bs = sm + 17536;      // 8
    int tid = threadIdx.x;
    int b  = blockIdx.z;
    int oy = blockIdx.y * 30, ox = blockIdx.x * 30;

    // load x tile (zero-padded)
    for (int i = tid; i < 8192; i += 256) {
        int col = i & 31, r = (i >> 5) & 31, c = i >> 10;
        int gy = oy - 1 + r, gx = ox - 1 + col;
        float v = 0.f;
        if (gy >= 0 && gy < HH && gx >= 0 && gx < WW)
            v = x[((size_t)(b*8 + c)*HH + gy)*WW + gx];
        xs[i] = v;
    }

    for (int phase = 0; phase < 3; phase++) {
        const float *wk, *bk, *pk;
        int k, PH, PW, cg;
        if (phase == 0)      { wk = w5;  bk = b5;  pk = p5_buf;  k = 5;  PH = 60; PW = 60; cg = 0;  }
        else if (phase == 1) { wk = w10; bk = b10; pk = p10_buf; k = 10; PH = 30; PW = 30; cg = 8;  }
        else                 { wk = w15; bk = b15; pk = p15_buf; k = 15; PH = 20; PW = 20; cg = 16; }

        __syncthreads();  // previous phase consumers done before overwriting us/ws
        for (int i = tid; i < 8192; i += 256) {
            int col = i & 31, r = (i >> 5) & 31, c = i >> 10;
            int gy = oy - 1 + r, gx = ox - 1 + col;
            float v = 0.f;
            if (gy >= 0 && gy < HH && gx >= 0 && gx < WW)
                v = pk[((b*8 + c)*PH + gy / k)*PW + gx / k];
            us[i] = v;
        }
        for (int i = tid; i < 1152; i += 256) ws[i] = wk[i];
        if (tid < 8) bs[tid] = bk[tid];
        __syncthreads();

        for (int p = tid; p < 450; p += 256) {
            int row  = p / 15;
            int col0 = (p % 15) * 2;
            float a0[8], a1[8];
            #pragma unroll
            for (int o = 0; o < 8; o++) { a0[o] = bs[o]; a1[o] = bs[o]; }
            #pragma unroll
            for (int half = 0; half < 2; half++) {
                const float* src = half ? us : xs;
                #pragma unroll 2
                for (int ic = 0; ic < 8; ic++) {
                    float v[3][4];
                    #pragma unroll
                    for (int r = 0; r < 3; r++) {
                        const float* rp = src + ic*1024 + (row + r)*32 + col0;
                        float2 v0 = *reinterpret_cast<const float2*>(rp);
                        float2 v1 = *reinterpret_cast<const float2*>(rp + 2);
                        v[r][0] = v0.x; v[r][1] = v0.y; v[r][2] = v1.x; v[r][3] = v1.y;
                    }
                    #pragma unroll
                    for (int o = 0; o < 8; o++) {
                        const float* w = ws + ((o*16) + half*8 + ic)*9;
                        #pragma unroll
                        for (int r = 0; r < 3; r++)
                            #pragma unroll
                            for (int q = 0; q < 3; q++) {
                                float wv = w[r*3 + q];
                                a0[o] = fmaf(wv, v[r][q],     a0[o]);
                                a1[o] = fmaf(wv, v[r][q + 1], a1[o]);
                            }
                    }
                }
            }
            int gy = oy + row, gx = ox + col0;
            #pragma unroll
            for (int o = 0; o < 8; o++) {
                float2 st; st.x = a0[o]; st.y = a1[o];
                *reinterpret_cast<float2*>(
                    &g_buf[(((size_t)b*24 + cg + o)*HH + gy)*WW + gx]) = st;
            }
        }
    }
}

// ---------------- K2b: gated conv pair + partial BN stats ----------------
// dyn smem: gs[24*32*32] + wgs[1728] + wms[1728] + biases[16] = 28048 floats
__global__ void k_conv2(const float* __restrict__ gw, const float* __restrict__ gb,
                        const float* __restrict__ mw, const float* __restrict__ mb,
                        float* __restrict__ out) {
    extern __shared__ float sm[];
    float* gs  = sm;             // 24576
    float* wgs = sm + 24576;     // 1728
    float* wms = sm + 26304;     // 1728
    float* bgs = sm + 28032;     // 8
    float* bms = sm + 28040;     // 8
    int tid = threadIdx.x;
    int b  = blockIdx.z;
    int oy = blockIdx.y * 30, ox = blockIdx.x * 30;

    for (int i = tid; i < 24576; i += 256) {
        int col = i & 31, r = (i >> 5) & 31, c = i >> 10;
        int gy = oy - 1 + r, gx = ox - 1 + col;
        float v = 0.f;
        if (gy >= 0 && gy < HH && gx >= 0 && gx < WW)
            v = g_buf[(((size_t)b*24 + c)*HH + gy)*WW + gx];
        gs[i] = v;
    }
    for (int i = tid; i < 1728; i += 256) { wgs[i] = gw[i]; wms[i] = mw[i]; }
    if (tid < 8) { bgs[tid] = gb[tid]; bms[tid] = mb[tid]; }
    __syncthreads();

    float lsum[8], lss[8];
    #pragma unroll
    for (int o = 0; o < 8; o++) { lsum[o] = 0.f; lss[o] = 0.f; }

    for (int p = tid; p < 450; p += 256) {
        int row  = p / 15;
        int col0 = (p % 15) * 2;
        float g0[8], g1[8], m0[8], m1[8];
        #pragma unroll
        for (int o = 0; o < 8; o++) {
            g0[o] = bgs[o]; g1[o] = bgs[o];
            m0[o] = bms[o]; m1[o] = bms[o];
        }
        #pragma unroll 1
        for (int ic = 0; ic < 24; ic++) {
            float v[3][4];
            #pragma unroll
            for (int r = 0; r < 3; r++) {
                const float* rp = gs + ic*1024 + (row + r)*32 + col0;
                float2 v0 = *reinterpret_cast<const float2*>(rp);
                float2 v1 = *reinterpret_cast<const float2*>(rp + 2);
                v[r][0] = v0.x; v[r][1] = v0.y; v[r][2] = v1.x; v[r][3] = v1.y;
            }
            #pragma unroll
            for (int o = 0; o < 8; o++) {
                const float* wg = wgs + (o*24 + ic)*9;
                const float* wm = wms + (o*24 + ic)*9;
                #pragma unroll
                for (int r = 0; r < 3; r++)
                    #pragma unroll
                    for (int q = 0; q < 3; q++) {
                        float wgv = wg[r*3 + q];
                        float wmv = wm[r*3 + q];
                        g0[o] = fmaf(wgv, v[r][q],     g0[o]);
                        g1[o] = fmaf(wgv, v[r][q + 1], g1[o]);
                        m0[o] = fmaf(wmv, v[r][q],     m0[o]);
                        m1[o] = fmaf(wmv, v[r][q + 1], m1[o]);
                    }
            }
        }
        int gy = oy + row, gx = ox + col0;
        #pragma unroll
        for (int o = 0; o < 8; o++) {
            float y0 = g0[o] / (1.f + __expf(-m0[o]));  // g * sigmoid(m)
            float y1 = g1[o] / (1.f + __expf(-m1[o]));
            float2 st; st.x = y0; st.y = y1;
            *reinterpret_cast<float2*>(
                &out[(((size_t)b*8 + o)*HH + gy)*WW + gx]) = st;
            lsum[o] += y0 + y1;
            lss[o]  += y0*y0 + y1*y1;
        }
    }

    // deterministic block reduction of (sum, sumsq) per channel
    #pragma unroll
    for (int o = 0; o < 8; o++)
        for (int d = 16; d > 0; d >>= 1) {
            lsum[o] += __shfl_xor_sync(0xffffffffu, lsum[o], d);
            lss[o]  += __shfl_xor_sync(0xffffffffu, lss[o],  d);
        }
    __syncthreads();  // done reading gs; reuse it
    int wid = tid >> 5, lane = tid & 31;
    if (lane == 0) {
        #pragma unroll
        for (int o = 0; o < 8; o++) {
            gs[wid*16 + o]     = lsum[o];
            gs[wid*16 + 8 + o] = lss[o];
        }
    }
    __syncthreads();
    if (tid < 16) {
        float s = 0.f;
        #pragma unroll
        for (int w2 = 0; w2 < 8; w2++) s += gs[w2*16 + tid];
        int blin = (blockIdx.z * 10 + blockIdx.y) * 10 + blockIdx.x;
        part_buf[blin*16 + tid] = s;
    }
}

// ---------------- K3: final BN stats (deterministic, double) ----------------
__global__ void k_stats(const float* __restrict__ gamma, const float* __restrict__ beta) {
    __shared__ double red[16*9];
    int tid = threadIdx.x;
    int wid = tid >> 5, lane = tid & 31;
    double acc[16];
    #pragma unroll
    for (int v = 0; v < 16; v++) acc[v] = 0.0;
    for (int i = tid; i < 3200; i += 256) {
        #pragma unroll
        for (int v = 0; v < 16; v++) acc[v] += (double)part_buf[i*16 + v];
    }
    #pragma unroll
    for (int v = 0; v < 16; v++)
        for (int d = 16; d > 0; d >>= 1)
            acc[v] += __shfl_xor_sync(0xffffffffu, acc[v], d);
    if (lane == 0) {
        #pragma unroll
        for (int v = 0; v < 16; v++) red[wid*16 + v] = acc[v];
    }
    __syncthreads();
    if (tid < 16) {
        double s = 0.0;
        #pragma unroll
        for (int w = 0; w < 8; w++) s += red[w*16 + tid];
        red[128 + tid] = s;
    }
    __syncthreads();
    if (tid < 8) {
        const double N = 2880000.0;
        double mean = red[128 + tid] / N;
        double ex2  = red[136 + tid] / N;
        double var  = ex2 - mean * mean;
        double scale = (double)gamma[tid] / sqrt(var + 1e-5);
        double shift = (double)beta[tid] - mean * scale;
        bn_buf[tid]     = (float)scale;
        bn_buf[8 + tid] = (float)shift;
    }
}

// ---------------- K4: in-place normalize ----------------
__global__ void k_norm(float* __restrict__ out) {
    int i = blockIdx.x * blockDim.x + threadIdx.x;
    if (i >= 5760000) return;                 // 23.04M / 4
    int c = (i / 22500) & 7;                  // 90000/4 floats4 per (b,c)
    float sc = bn_buf[c], sh = bn_buf[8 + c];
    float4 v = reinterpret_cast<float4*>(out)[i];
    v.x = v.x * sc + sh;
    v.y = v.y * sc + sh;
    v.z = v.z * sc + sh;
    v.w = v.w * sc + sh;
    reinterpret_cast<float4*>(out)[i] = v;
}

// ---------------- launch ----------------
extern "C" void kernel_launch(void* const* d_in, const int* in_sizes, int n_in,
                              void* d_out, int out_size) {
    const float* x    = (const float*)d_in[0];
    const float* w5   = (const float*)d_in[1];
    const float* b5   = (const float*)d_in[2];
    const float* w10  = (const float*)d_in[3];
    const float* b10  = (const float*)d_in[4];
    const float* w15  = (const float*)d_in[5];
    const float* b15  = (const float*)d_in[6];
    const float* gw   = (const float*)d_in[7];
    const float* gb   = (const float*)d_in[8];
    const float* mw   = (const float*)d_in[9];
    const float* mb   = (const float*)d_in[10];
    const float* gamma= (const float*)d_in[11];
    const float* beta = (const float*)d_in[12];
    float* out = (float*)d_out;

    cudaFuncSetAttribute(k_conv1, cudaFuncAttributeMaxDynamicSharedMemorySize, 17544*4);
    cudaFuncSetAttribute(k_conv2, cudaFuncAttributeMaxDynamicSharedMemorySize, 28048*4);

    k_pool5   <<<(921600 + 255) / 256, 256>>>(x);
    k_poolrest<<<(332800 + 255) / 256, 256>>>();

    dim3 grid(10, 10, 32);
    k_conv1<<<grid, 256, 17544*4>>>(x, w5, b5, w10, b10, w15, b15);
    k_conv2<<<grid, 256, 28048*4>>>(gw, gb, mw, mb, out);

    k_stats<<<1, 256>>>(gamma, beta);
    k_norm <<<(5760000 + 255) / 256, 256>>>(out);
}